// round 8
// baseline (speedup 1.0000x reference)
#include <cuda_runtime.h>
#include <cstdint>
#include <math.h>

// Problem constants
constexpr int NB = 4;       // batch
constexpr int S  = 2048;    // seq
constexpr int D  = 1024;    // model dim
constexpr int H  = 16;      // heads
constexpr int DK = 64;      // head dim
constexpr int M  = NB * S;  // 8192 rows

// Intermediate buffers (allocation-free rule: device globals)
__device__ float g_Q[(size_t)M * D];
__device__ float g_K[(size_t)M * D];
__device__ float g_V[(size_t)M * D];
__device__ float g_A[(size_t)M * D];

// ---------------------------------------------------------------------------
__device__ __forceinline__ uint32_t tf32r(float x) {
    uint32_t y;
    asm("cvt.rna.tf32.f32 %0, %1;" : "=r"(y) : "f"(x));
    return y;
}
__device__ __forceinline__ float tf32f(float x) {
    return __uint_as_float(tf32r(x));
}

__device__ __forceinline__ void mma16n8k8(float* d, const uint32_t* a,
                                          uint32_t b0, uint32_t b1) {
    asm volatile(
        "mma.sync.aligned.m16n8k8.row.col.f32.tf32.tf32.f32 "
        "{%0,%1,%2,%3}, {%4,%5,%6,%7}, {%8,%9}, {%0,%1,%2,%3};"
        : "+f"(d[0]), "+f"(d[1]), "+f"(d[2]), "+f"(d[3])
        : "r"(a[0]), "r"(a[1]), "r"(a[2]), "r"(a[3]), "r"(b0), "r"(b1));
}

// ===========================================================================
// tf32 mma.sync GEMM body (same algorithm as R6/R7 passing version).
// ===========================================================================
constexpr int AP = 36;
constexpr int BP = 136;
constexpr int ASZ = 128 * AP;
constexpr int BSZ = 32 * BP;
constexpr int BUFF = ASZ + BSZ;
constexpr int GSM_BYTES = 2 * BUFF * 4;  // 71680 B

__device__ __forceinline__ void gemm_body(
    const float* __restrict__ A, const float* __restrict__ W,
    float* __restrict__ C, float* sm)
{
    const int tid  = threadIdx.x;
    const int lane = tid & 31;
    const int wid  = tid >> 5;
    const int wm   = wid & 3;
    const int wn   = wid >> 2;
    const int g    = lane >> 2;
    const int t    = lane & 3;
    const int m0   = blockIdx.y * 128;
    const int n0   = blockIdx.x * 128;

    float acc[2][8][4];
#pragma unroll
    for (int i = 0; i < 2; i++)
#pragma unroll
        for (int j = 0; j < 8; j++)
#pragma unroll
            for (int c = 0; c < 4; c++) acc[i][j][c] = 0.f;

    float4 ra[4], rb[4];

    auto ldg_chunk = [&](int k0) {
#pragma unroll
        for (int i = 0; i < 4; i++) {
            int id = tid + i * 256;
            int r = id >> 3, c4 = id & 7;
            ra[i] = *(const float4*)(A + (size_t)(m0 + r) * D + k0 + c4 * 4);
        }
#pragma unroll
        for (int i = 0; i < 4; i++) {
            int id = tid + i * 256;
            int r = id >> 5, c4 = id & 31;
            rb[i] = *(const float4*)(W + (size_t)(k0 + r) * D + n0 + c4 * 4);
        }
    };
    auto sts_chunk = [&](int p) {
        float* sA = sm + p * BUFF;
        float* sB = sA + ASZ;
#pragma unroll
        for (int i = 0; i < 4; i++) {
            int id = tid + i * 256;
            int r = id >> 3, c4 = id & 7;
            uint4 u = make_uint4(tf32r(ra[i].x), tf32r(ra[i].y),
                                 tf32r(ra[i].z), tf32r(ra[i].w));
            *(uint4*)(sA + r * AP + c4 * 4) = u;
        }
#pragma unroll
        for (int i = 0; i < 4; i++) {
            int id = tid + i * 256;
            int r = id >> 5, c4 = id & 31;
            uint4 u = make_uint4(tf32r(rb[i].x), tf32r(rb[i].y),
                                 tf32r(rb[i].z), tf32r(rb[i].w));
            *(uint4*)(sB + r * BP + c4 * 4) = u;
        }
    };

    ldg_chunk(0);
    sts_chunk(0);
    __syncthreads();

    for (int ch = 0; ch < 32; ch++) {
        const int p = ch & 1;
        if (ch + 1 < 32) ldg_chunk((ch + 1) * 32);

        const float* cA = sm + p * BUFF;
        const float* cB = cA + ASZ;
#pragma unroll
        for (int ks = 0; ks < 4; ks++) {
            const int kk = ks * 8;
            uint32_t af[2][4];
#pragma unroll
            for (int i = 0; i < 2; i++) {
                int row = wm * 32 + i * 16 + g;
                af[i][0] = __float_as_uint(cA[(row)     * AP + kk + t]);
                af[i][1] = __float_as_uint(cA[(row + 8) * AP + kk + t]);
                af[i][2] = __float_as_uint(cA[(row)     * AP + kk + t + 4]);
                af[i][3] = __float_as_uint(cA[(row + 8) * AP + kk + t + 4]);
            }
#pragma unroll
            for (int j = 0; j < 8; j++) {
                int col = wn * 64 + j * 8 + g;
                uint32_t b0 = __float_as_uint(cB[(kk + t)     * BP + col]);
                uint32_t b1 = __float_as_uint(cB[(kk + t + 4) * BP + col]);
                mma16n8k8(acc[0][j], af[0], b0, b1);
                mma16n8k8(acc[1][j], af[1], b0, b1);
            }
        }
        if (ch + 1 < 32) sts_chunk((ch + 1) & 1);
        __syncthreads();
    }

#pragma unroll
    for (int i = 0; i < 2; i++) {
        int row = m0 + wm * 32 + i * 16 + g;
#pragma unroll
        for (int j = 0; j < 8; j++) {
            int col = n0 + wn * 64 + j * 8 + 2 * t;
            *(float2*)&C[(size_t)row * D + col] =
                make_float2(acc[i][j][0], acc[i][j][1]);
            *(float2*)&C[(size_t)(row + 8) * D + col] =
                make_float2(acc[i][j][2], acc[i][j][3]);
        }
    }
}

__global__ __launch_bounds__(256, 2) void gemm_mma(
    const float* __restrict__ A, const float* __restrict__ W,
    float* __restrict__ C)
{
    extern __shared__ float sm[];
    gemm_body(A, W, C, sm);
}

// Merged QKV projection: blockIdx.z selects (input, weight, output).
__global__ __launch_bounds__(256, 2) void gemm_qkv(
    const float* __restrict__ A0, const float* __restrict__ W0, float* __restrict__ C0,
    const float* __restrict__ A1, const float* __restrict__ W1, float* __restrict__ C1,
    const float* __restrict__ A2, const float* __restrict__ W2, float* __restrict__ C2)
{
    extern __shared__ float sm[];
    const int z = blockIdx.z;
    const float* A = (z == 0) ? A0 : (z == 1) ? A1 : A2;
    const float* W = (z == 0) ? W0 : (z == 1) ? W1 : W2;
    float*       C = (z == 0) ? C0 : (z == 1) ? C1 : C2;
    gemm_body(A, W, C, sm);
}

// ===========================================================================
// Causal flash attention with tf32 mma.sync — 8 warps, each m16 x n64.
// QT=128 q-rows per CTA. Natural [token][d] smem layouts, pitch 68.
// P round-trips through smem (tf32); sP rows warp-private -> syncwarp only.
// smem 104448 B; launch_bounds(256,2) -> <=128 regs -> 2 CTA/SM = 16 warps.
// ===========================================================================
constexpr int FP = 68;
constexpr int FSM_BYTES = (128 * FP + 64 * FP + 64 * FP + 128 * FP) * 4;  // 104448

__global__ __launch_bounds__(256, 2) void flash_mma(
    const float* __restrict__ Q, const float* __restrict__ K,
    const float* __restrict__ V, float* __restrict__ O)
{
    extern __shared__ float sm[];
    float* sQ = sm;                    // [128][FP]
    float* sK = sQ + 128 * FP;         // [64][FP]
    float* sV = sK + 64 * FP;          // [64][FP]
    float* sP = sV + 64 * FP;          // [128][FP]

    const int tid  = threadIdx.x;
    const int w    = tid >> 5;
    const int lane = tid & 31;
    const int g    = lane >> 2;
    const int t    = lane & 3;
    const int bh   = blockIdx.y;
    const int b    = bh >> 4;
    const int h    = bh & 15;
    const int qi   = 15 - blockIdx.x;      // heavy tiles first
    const int q0   = qi * 128;

    const size_t base = (size_t)b * S * D + (size_t)h * DK;
    const float* Qb = Q + base;
    const float* Kb = K + base;
    const float* Vb = V + base;

    // Load Q tile [128][64] -> sQ (tf32, natural layout)
#pragma unroll
    for (int i = 0; i < 8; i++) {
        int id = tid + i * 256;
        int r = id >> 4, c = (id & 15) << 2;
        float4 v4 = *(const float4*)&Qb[(size_t)(q0 + r) * D + c];
        uint4 u = make_uint4(tf32r(v4.x), tf32r(v4.y), tf32r(v4.z), tf32r(v4.w));
        *(uint4*)&sQ[r * FP + c] = u;
    }

    float o[8][4];
    float mr0 = -1e30f, mr1 = -1e30f, lr0 = 0.f, lr1 = 0.f;
#pragma unroll
    for (int j = 0; j < 8; j++)
#pragma unroll
        for (int c = 0; c < 4; c++) o[j][c] = 0.f;

    const int rowb = w * 16 + g;          // local q-row of reg row g
    const int nk = 2 * qi + 2;
    for (int kt = 0; kt < nk; kt++) {
        const int k0 = kt * 64;
        __syncthreads();  // prior PV done reading sK/sV
        // Load K,V tiles [64][64] -> smem (tf32, natural)
#pragma unroll
        for (int i = 0; i < 4; i++) {
            int id = tid + i * 256;
            int r = id >> 4, c = (id & 15) << 2;
            float4 k4 = *(const float4*)&Kb[(size_t)(k0 + r) * D + c];
            uint4 uk = make_uint4(tf32r(k4.x), tf32r(k4.y), tf32r(k4.z), tf32r(k4.w));
            *(uint4*)&sK[r * FP + c] = uk;
            float4 v4 = *(const float4*)&Vb[(size_t)(k0 + r) * D + c];
            uint4 uv = make_uint4(tf32r(v4.x), tf32r(v4.y), tf32r(v4.z), tf32r(v4.w));
            *(uint4*)&sV[r * FP + c] = uv;
        }
        __syncthreads();

        // ---- S = Q K^T (m16 x n64 per warp) ----
        float s[8][4];
#pragma unroll
        for (int j = 0; j < 8; j++)
#pragma unroll
            for (int c = 0; c < 4; c++) s[j][c] = 0.f;

#pragma unroll
        for (int kk = 0; kk < 8; kk++) {
            const int d8 = kk * 8;
            uint32_t am[4];
            {
                int rb = rowb * FP + d8 + t;
                am[0] = __float_as_uint(sQ[rb]);
                am[1] = __float_as_uint(sQ[rb + 8 * FP]);
                am[2] = __float_as_uint(sQ[rb + 4]);
                am[3] = __float_as_uint(sQ[rb + 8 * FP + 4]);
            }
#pragma unroll
            for (int jj = 0; jj < 8; jj++) {
                uint32_t b0 = __float_as_uint(sK[(jj * 8 + g) * FP + d8 + t]);
                uint32_t b1 = __float_as_uint(sK[(jj * 8 + g) * FP + d8 + t + 4]);
                mma16n8k8(s[jj], am, b0, b1);
            }
        }

        // ---- scale + causal mask ----
        const float scale = 0.125f;  // 1/sqrt(64)
        const bool domask = (k0 >= q0);
        const int r0 = q0 + rowb;
        const int r1 = r0 + 8;
#pragma unroll
        for (int jj = 0; jj < 8; jj++) {
            int c0 = k0 + jj * 8 + 2 * t;
            int c1 = c0 + 1;
            s[jj][0] *= scale; s[jj][1] *= scale;
            s[jj][2] *= scale; s[jj][3] *= scale;
            if (domask) {
                if (c0 > r0) s[jj][0] = -1e30f;
                if (c1 > r0) s[jj][1] = -1e30f;
                if (c0 > r1) s[jj][2] = -1e30f;
                if (c1 > r1) s[jj][3] = -1e30f;
            }
        }

        // ---- online softmax (rows warp-private; quad-lane reduce) ----
        {
            float mx0 = -1e30f, mx1 = -1e30f;
#pragma unroll
            for (int jj = 0; jj < 8; jj++) {
                mx0 = fmaxf(mx0, fmaxf(s[jj][0], s[jj][1]));
                mx1 = fmaxf(mx1, fmaxf(s[jj][2], s[jj][3]));
            }
            mx0 = fmaxf(mx0, __shfl_xor_sync(0xffffffffu, mx0, 1));
            mx0 = fmaxf(mx0, __shfl_xor_sync(0xffffffffu, mx0, 2));
            mx1 = fmaxf(mx1, __shfl_xor_sync(0xffffffffu, mx1, 1));
            mx1 = fmaxf(mx1, __shfl_xor_sync(0xffffffffu, mx1, 2));
            float mn0 = fmaxf(mr0, mx0);
            float mn1 = fmaxf(mr1, mx1);
            float al0 = __expf(mr0 - mn0);
            float al1 = __expf(mr1 - mn1);
            mr0 = mn0; mr1 = mn1;
            float rs0 = 0.f, rs1 = 0.f;
            int rb = rowb * FP;
#pragma unroll
            for (int jj = 0; jj < 8; jj++) {
                float p0 = __expf(s[jj][0] - mn0);
                float p1 = __expf(s[jj][1] - mn0);
                float p2 = __expf(s[jj][2] - mn1);
                float p3 = __expf(s[jj][3] - mn1);
                rs0 += p0 + p1;
                rs1 += p2 + p3;
                int cc = jj * 8 + 2 * t;
                *(float2*)&sP[rb + cc]          = make_float2(tf32f(p0), tf32f(p1));
                *(float2*)&sP[rb + 8 * FP + cc] = make_float2(tf32f(p2), tf32f(p3));
                o[jj][0] *= al0; o[jj][1] *= al0;
                o[jj][2] *= al1; o[jj][3] *= al1;
            }
            rs0 += __shfl_xor_sync(0xffffffffu, rs0, 1);
            rs0 += __shfl_xor_sync(0xffffffffu, rs0, 2);
            rs1 += __shfl_xor_sync(0xffffffffu, rs1, 1);
            rs1 += __shfl_xor_sync(0xffffffffu, rs1, 2);
            lr0 = lr0 * al0 + rs0;
            lr1 = lr1 * al1 + rs1;
        }
        __syncwarp();

        // ---- O += P V ----
#pragma unroll
        for (int kk = 0; kk < 8; kk++) {
            const int k8 = kk * 8;
            uint32_t am[4];
            {
                int rb = rowb * FP + k8 + t;
                am[0] = __float_as_uint(sP[rb]);
                am[1] = __float_as_uint(sP[rb + 8 * FP]);
                am[2] = __float_as_uint(sP[rb + 4]);
                am[3] = __float_as_uint(sP[rb + 8 * FP + 4]);
            }
#pragma unroll
            for (int jj = 0; jj < 8; jj++) {
                uint32_t b0 = __float_as_uint(sV[(k8 + t) * FP + jj * 8 + g]);
                uint32_t b1 = __float_as_uint(sV[(k8 + t + 4) * FP + jj * 8 + g]);
                mma16n8k8(o[jj], am, b0, b1);
            }
        }
        __syncwarp();  // P fully consumed before next iteration overwrites
    }

    // ---- normalize + store ----
    float* Ob = O + base;
    {
        float inv0 = 1.f / lr0;
        float inv1 = 1.f / lr1;
        int r0 = q0 + rowb;
#pragma unroll
        for (int jj = 0; jj < 8; jj++) {
            int dd = jj * 8 + 2 * t;
            *(float2*)&Ob[(size_t)r0 * D + dd] =
                make_float2(o[jj][0] * inv0, o[jj][1] * inv0);
            *(float2*)&Ob[(size_t)(r0 + 8) * D + dd] =
                make_float2(o[jj][2] * inv1, o[jj][3] * inv1);
        }
    }
}

// ---------------------------------------------------------------------------
extern "C" void kernel_launch(void* const* d_in, const int* in_sizes, int n_in,
                              void* d_out, int out_size)
{
    const float* big[3] = {nullptr, nullptr, nullptr};
    const float* w[4]   = {nullptr, nullptr, nullptr, nullptr};
    int nbig = 0, nw = 0;
    for (int i = 0; i < n_in; i++) {
        int sz = in_sizes[i];
        if (sz == M * D) {
            if (nbig < 3) big[nbig++] = (const float*)d_in[i];
        } else if (sz == D * D) {
            if (nw < 4) w[nw++] = (const float*)d_in[i];
        }
    }
    const float* q = big[0];
    const float* k = big[1];
    const float* v = big[2];
    const float* Wq = w[0];
    const float* Wk = w[1];
    const float* Wv = w[2];
    const float* Wo = w[3];
    float* out = (float*)d_out;

    float *Qp, *Kp, *Vp, *Ap;
    cudaGetSymbolAddress((void**)&Qp, g_Q);
    cudaGetSymbolAddress((void**)&Kp, g_K);
    cudaGetSymbolAddress((void**)&Vp, g_V);
    cudaGetSymbolAddress((void**)&Ap, g_A);

    cudaFuncSetAttribute(gemm_mma, cudaFuncAttributeMaxDynamicSharedMemorySize, GSM_BYTES);
    cudaFuncSetAttribute(gemm_qkv, cudaFuncAttributeMaxDynamicSharedMemorySize, GSM_BYTES);
    cudaFuncSetAttribute(flash_mma, cudaFuncAttributeMaxDynamicSharedMemorySize, FSM_BYTES);

    dim3 gq(D / 128, M / 128, 3);  // (8, 64, 3) merged QKV
    gemm_qkv<<<gq, 256, GSM_BYTES>>>(q, Wq, Qp, k, Wk, Kp, v, Wv, Vp);

    dim3 ga(S / 128, NB * H);  // (16, 64)
    flash_mma<<<ga, 256, FSM_BYTES>>>(Qp, Kp, Vp, Ap);

    dim3 gt(D / 128, M / 128);  // (8, 64)
    gemm_mma<<<gt, 256, GSM_BYTES>>>(Ap, Wo, out);
}

// round 10
// speedup vs baseline: 1.1008x; 1.1008x over previous
#include <cuda_runtime.h>
#include <cstdint>
#include <math.h>

// Problem constants
constexpr int NB = 4;       // batch
constexpr int S  = 2048;    // seq
constexpr int D  = 1024;    // model dim
constexpr int H  = 16;      // heads
constexpr int DK = 64;      // head dim
constexpr int M  = NB * S;  // 8192 rows

// Intermediate buffers (allocation-free rule: device globals)
__device__ float g_Q[(size_t)M * D];
__device__ float g_K[(size_t)M * D];
__device__ float g_V[(size_t)M * D];
__device__ float g_A[(size_t)M * D];

// ---------------------------------------------------------------------------
__device__ __forceinline__ uint32_t tf32r(float x) {
    uint32_t y;
    asm("cvt.rna.tf32.f32 %0, %1;" : "=r"(y) : "f"(x));
    return y;
}
__device__ __forceinline__ float tf32f(float x) {
    return __uint_as_float(tf32r(x));
}

__device__ __forceinline__ void mma16n8k8(float* d, const uint32_t* a,
                                          uint32_t b0, uint32_t b1) {
    asm volatile(
        "mma.sync.aligned.m16n8k8.row.col.f32.tf32.tf32.f32 "
        "{%0,%1,%2,%3}, {%4,%5,%6,%7}, {%8,%9}, {%0,%1,%2,%3};"
        : "+f"(d[0]), "+f"(d[1]), "+f"(d[2]), "+f"(d[3])
        : "r"(a[0]), "r"(a[1]), "r"(a[2]), "r"(a[3]), "r"(b0), "r"(b1));
}

// ===========================================================================
// tf32 mma.sync GEMM body (R6/R7 passing algorithm).
// ===========================================================================
constexpr int AP = 36;
constexpr int BP = 136;
constexpr int ASZ = 128 * AP;
constexpr int BSZ = 32 * BP;
constexpr int BUFF = ASZ + BSZ;
constexpr int GSM_BYTES = 2 * BUFF * 4;  // 71680 B

__device__ __forceinline__ void gemm_body(
    const float* __restrict__ A, const float* __restrict__ W,
    float* __restrict__ C, float* sm)
{
    const int tid  = threadIdx.x;
    const int lane = tid & 31;
    const int wid  = tid >> 5;
    const int wm   = wid & 3;
    const int wn   = wid >> 2;
    const int g    = lane >> 2;
    const int t    = lane & 3;
    const int m0   = blockIdx.y * 128;
    const int n0   = blockIdx.x * 128;

    float acc[2][8][4];
#pragma unroll
    for (int i = 0; i < 2; i++)
#pragma unroll
        for (int j = 0; j < 8; j++)
#pragma unroll
            for (int c = 0; c < 4; c++) acc[i][j][c] = 0.f;

    float4 ra[4], rb[4];

    auto ldg_chunk = [&](int k0) {
#pragma unroll
        for (int i = 0; i < 4; i++) {
            int id = tid + i * 256;
            int r = id >> 3, c4 = id & 7;
            ra[i] = *(const float4*)(A + (size_t)(m0 + r) * D + k0 + c4 * 4);
        }
#pragma unroll
        for (int i = 0; i < 4; i++) {
            int id = tid + i * 256;
            int r = id >> 5, c4 = id & 31;
            rb[i] = *(const float4*)(W + (size_t)(k0 + r) * D + n0 + c4 * 4);
        }
    };
    auto sts_chunk = [&](int p) {
        float* sA = sm + p * BUFF;
        float* sB = sA + ASZ;
#pragma unroll
        for (int i = 0; i < 4; i++) {
            int id = tid + i * 256;
            int r = id >> 3, c4 = id & 7;
            uint4 u = make_uint4(tf32r(ra[i].x), tf32r(ra[i].y),
                                 tf32r(ra[i].z), tf32r(ra[i].w));
            *(uint4*)(sA + r * AP + c4 * 4) = u;
        }
#pragma unroll
        for (int i = 0; i < 4; i++) {
            int id = tid + i * 256;
            int r = id >> 5, c4 = id & 31;
            uint4 u = make_uint4(tf32r(rb[i].x), tf32r(rb[i].y),
                                 tf32r(rb[i].z), tf32r(rb[i].w));
            *(uint4*)(sB + r * BP + c4 * 4) = u;
        }
    };

    ldg_chunk(0);
    sts_chunk(0);
    __syncthreads();

    for (int ch = 0; ch < 32; ch++) {
        const int p = ch & 1;
        if (ch + 1 < 32) ldg_chunk((ch + 1) * 32);

        const float* cA = sm + p * BUFF;
        const float* cB = cA + ASZ;
#pragma unroll
        for (int ks = 0; ks < 4; ks++) {
            const int kk = ks * 8;
            uint32_t af[2][4];
#pragma unroll
            for (int i = 0; i < 2; i++) {
                int row = wm * 32 + i * 16 + g;
                af[i][0] = __float_as_uint(cA[(row)     * AP + kk + t]);
                af[i][1] = __float_as_uint(cA[(row + 8) * AP + kk + t]);
                af[i][2] = __float_as_uint(cA[(row)     * AP + kk + t + 4]);
                af[i][3] = __float_as_uint(cA[(row + 8) * AP + kk + t + 4]);
            }
#pragma unroll
            for (int j = 0; j < 8; j++) {
                int col = wn * 64 + j * 8 + g;
                uint32_t b0 = __float_as_uint(cB[(kk + t)     * BP + col]);
                uint32_t b1 = __float_as_uint(cB[(kk + t + 4) * BP + col]);
                mma16n8k8(acc[0][j], af[0], b0, b1);
                mma16n8k8(acc[1][j], af[1], b0, b1);
            }
        }
        if (ch + 1 < 32) sts_chunk((ch + 1) & 1);
        __syncthreads();
    }

#pragma unroll
    for (int i = 0; i < 2; i++) {
        int row = m0 + wm * 32 + i * 16 + g;
#pragma unroll
        for (int j = 0; j < 8; j++) {
            int col = n0 + wn * 64 + j * 8 + 2 * t;
            *(float2*)&C[(size_t)row * D + col] =
                make_float2(acc[i][j][0], acc[i][j][1]);
            *(float2*)&C[(size_t)(row + 8) * D + col] =
                make_float2(acc[i][j][2], acc[i][j][3]);
        }
    }
}

__global__ __launch_bounds__(256, 2) void gemm_mma(
    const float* __restrict__ A, const float* __restrict__ W,
    float* __restrict__ C)
{
    extern __shared__ float sm[];
    gemm_body(A, W, C, sm);
}

// Merged QKV projection: blockIdx.z selects (input, weight, output).
__global__ __launch_bounds__(256, 2) void gemm_qkv(
    const float* __restrict__ A0, const float* __restrict__ W0, float* __restrict__ C0,
    const float* __restrict__ A1, const float* __restrict__ W1, float* __restrict__ C1,
    const float* __restrict__ A2, const float* __restrict__ W2, float* __restrict__ C2)
{
    extern __shared__ float sm[];
    const int z = blockIdx.z;
    const float* A = (z == 0) ? A0 : (z == 1) ? A1 : A2;
    const float* W = (z == 0) ? W0 : (z == 1) ? W1 : W2;
    float*       C = (z == 0) ? C0 : (z == 1) ? C1 : C2;
    gemm_body(A, W, C, sm);
}

// ===========================================================================
// Causal flash attention with tf32 mma.sync (R7 passing config):
// QT=128 q-rows per CTA, 4 warps (each m32 = 2 m16 tiles, full n=64) —
// B-fragments amortized across 2 m-tiles per warp (key to crossbar budget).
// All smem natural [token][d], pitch 68. P round-trips through smem (tf32);
// sP rows warp-private -> syncwarp only. smem 104448 B -> 2 CTA/SM.
// ===========================================================================
constexpr int FP = 68;
constexpr int FSM_BYTES = (128 * FP + 64 * FP + 64 * FP + 128 * FP) * 4;  // 104448

__global__ __launch_bounds__(128, 1) void flash_mma(
    const float* __restrict__ Q, const float* __restrict__ K,
    const float* __restrict__ V, float* __restrict__ O)
{
    extern __shared__ float sm[];
    float* sQ = sm;                    // [128][FP]
    float* sK = sQ + 128 * FP;         // [64][FP]
    float* sV = sK + 64 * FP;          // [64][FP]
    float* sP = sV + 64 * FP;          // [128][FP]

    const int tid  = threadIdx.x;
    const int w    = tid >> 5;
    const int lane = tid & 31;
    const int g    = lane >> 2;
    const int t    = lane & 3;
    const int bh   = blockIdx.y;
    const int b    = bh >> 4;
    const int h    = bh & 15;
    const int qi   = 15 - blockIdx.x;      // heavy tiles first
    const int q0   = qi * 128;

    const size_t base = (size_t)b * S * D + (size_t)h * DK;
    const float* Qb = Q + base;
    const float* Kb = K + base;
    const float* Vb = V + base;

    // Load Q tile [128][64] -> sQ (tf32, natural layout)
#pragma unroll
    for (int i = 0; i < 16; i++) {
        int id = tid + i * 128;
        int r = id >> 4, c = (id & 15) << 2;
        float4 v4 = *(const float4*)&Qb[(size_t)(q0 + r) * D + c];
        uint4 u = make_uint4(tf32r(v4.x), tf32r(v4.y), tf32r(v4.z), tf32r(v4.w));
        *(uint4*)&sQ[r * FP + c] = u;
    }

    float o[2][8][4];
    float mr[2][2], lr[2][2];
#pragma unroll
    for (int i = 0; i < 2; i++) {
        mr[i][0] = -1e30f; mr[i][1] = -1e30f;
        lr[i][0] = 0.f;    lr[i][1] = 0.f;
#pragma unroll
        for (int j = 0; j < 8; j++)
#pragma unroll
            for (int c = 0; c < 4; c++) o[i][j][c] = 0.f;
    }

    const int rowb0 = w * 32 + g;          // local row of mtile 0, reg row g
    const int nk = 2 * qi + 2;
    for (int kt = 0; kt < nk; kt++) {
        const int k0 = kt * 64;
        __syncthreads();  // prior PV done reading sK/sV
        // Load K,V tiles [64][64] -> smem (tf32, natural)
#pragma unroll
        for (int i = 0; i < 8; i++) {
            int id = tid + i * 128;
            int r = id >> 4, c = (id & 15) << 2;
            float4 k4 = *(const float4*)&Kb[(size_t)(k0 + r) * D + c];
            uint4 uk = make_uint4(tf32r(k4.x), tf32r(k4.y), tf32r(k4.z), tf32r(k4.w));
            *(uint4*)&sK[r * FP + c] = uk;
            float4 v4 = *(const float4*)&Vb[(size_t)(k0 + r) * D + c];
            uint4 uv = make_uint4(tf32r(v4.x), tf32r(v4.y), tf32r(v4.z), tf32r(v4.w));
            *(uint4*)&sV[r * FP + c] = uv;
        }
        __syncthreads();

        // ---- S = Q K^T (m32 x n64 per warp) ----
        float s[2][8][4];
#pragma unroll
        for (int i = 0; i < 2; i++)
#pragma unroll
            for (int j = 0; j < 8; j++)
#pragma unroll
                for (int c = 0; c < 4; c++) s[i][j][c] = 0.f;

#pragma unroll
        for (int kk = 0; kk < 8; kk++) {
            const int d8 = kk * 8;
            uint32_t am[2][4];
#pragma unroll
            for (int i = 0; i < 2; i++) {
                int rb = (rowb0 + i * 16) * FP + d8 + t;
                am[i][0] = __float_as_uint(sQ[rb]);
                am[i][1] = __float_as_uint(sQ[rb + 8 * FP]);
                am[i][2] = __float_as_uint(sQ[rb + 4]);
                am[i][3] = __float_as_uint(sQ[rb + 8 * FP + 4]);
            }
#pragma unroll
            for (int jj = 0; jj < 8; jj++) {
                uint32_t b0 = __float_as_uint(sK[(jj * 8 + g) * FP + d8 + t]);
                uint32_t b1 = __float_as_uint(sK[(jj * 8 + g) * FP + d8 + t + 4]);
                mma16n8k8(s[0][jj], am[0], b0, b1);
                mma16n8k8(s[1][jj], am[1], b0, b1);
            }
        }

        // ---- scale + causal mask ----
        const float scale = 0.125f;  // 1/sqrt(64)
        const bool domask = (k0 >= q0);
#pragma unroll
        for (int i = 0; i < 2; i++) {
            int r0 = q0 + rowb0 + i * 16;
            int r1 = r0 + 8;
#pragma unroll
            for (int jj = 0; jj < 8; jj++) {
                int c0 = k0 + jj * 8 + 2 * t;
                int c1 = c0 + 1;
                s[i][jj][0] *= scale; s[i][jj][1] *= scale;
                s[i][jj][2] *= scale; s[i][jj][3] *= scale;
                if (domask) {
                    if (c0 > r0) s[i][jj][0] = -1e30f;
                    if (c1 > r0) s[i][jj][1] = -1e30f;
                    if (c0 > r1) s[i][jj][2] = -1e30f;
                    if (c1 > r1) s[i][jj][3] = -1e30f;
                }
            }
        }

        // ---- online softmax (rows warp-private; quad-lane reduce) ----
#pragma unroll
        for (int i = 0; i < 2; i++) {
            float mx0 = -1e30f, mx1 = -1e30f;
#pragma unroll
            for (int jj = 0; jj < 8; jj++) {
                mx0 = fmaxf(mx0, fmaxf(s[i][jj][0], s[i][jj][1]));
                mx1 = fmaxf(mx1, fmaxf(s[i][jj][2], s[i][jj][3]));
            }
            mx0 = fmaxf(mx0, __shfl_xor_sync(0xffffffffu, mx0, 1));
            mx0 = fmaxf(mx0, __shfl_xor_sync(0xffffffffu, mx0, 2));
            mx1 = fmaxf(mx1, __shfl_xor_sync(0xffffffffu, mx1, 1));
            mx1 = fmaxf(mx1, __shfl_xor_sync(0xffffffffu, mx1, 2));
            float mn0 = fmaxf(mr[i][0], mx0);
            float mn1 = fmaxf(mr[i][1], mx1);
            float al0 = __expf(mr[i][0] - mn0);
            float al1 = __expf(mr[i][1] - mn1);
            mr[i][0] = mn0; mr[i][1] = mn1;
            float rs0 = 0.f, rs1 = 0.f;
            int rb = (rowb0 + i * 16) * FP;
#pragma unroll
            for (int jj = 0; jj < 8; jj++) {
                float p0 = __expf(s[i][jj][0] - mn0);
                float p1 = __expf(s[i][jj][1] - mn0);
                float p2 = __expf(s[i][jj][2] - mn1);
                float p3 = __expf(s[i][jj][3] - mn1);
                rs0 += p0 + p1;
                rs1 += p2 + p3;
                int cc = jj * 8 + 2 * t;
                *(float2*)&sP[rb + cc]          = make_float2(tf32f(p0), tf32f(p1));
                *(float2*)&sP[rb + 8 * FP + cc] = make_float2(tf32f(p2), tf32f(p3));
#pragma unroll
                for (int c = 0; c < 2; c++) o[i][jj][c] *= al0;
#pragma unroll
                for (int c = 2; c < 4; c++) o[i][jj][c] *= al1;
            }
            rs0 += __shfl_xor_sync(0xffffffffu, rs0, 1);
            rs0 += __shfl_xor_sync(0xffffffffu, rs0, 2);
            rs1 += __shfl_xor_sync(0xffffffffu, rs1, 1);
            rs1 += __shfl_xor_sync(0xffffffffu, rs1, 2);
            lr[i][0] = lr[i][0] * al0 + rs0;
            lr[i][1] = lr[i][1] * al1 + rs1;
        }
        __syncwarp();

        // ---- O += P V ----
#pragma unroll
        for (int kk = 0; kk < 8; kk++) {
            const int k8 = kk * 8;
            uint32_t am[2][4];
#pragma unroll
            for (int i = 0; i < 2; i++) {
                int rb = (rowb0 + i * 16) * FP + k8 + t;
                am[i][0] = __float_as_uint(sP[rb]);
                am[i][1] = __float_as_uint(sP[rb + 8 * FP]);
                am[i][2] = __float_as_uint(sP[rb + 4]);
                am[i][3] = __float_as_uint(sP[rb + 8 * FP + 4]);
            }
#pragma unroll
            for (int jj = 0; jj < 8; jj++) {
                uint32_t b0 = __float_as_uint(sV[(k8 + t) * FP + jj * 8 + g]);
                uint32_t b1 = __float_as_uint(sV[(k8 + t + 4) * FP + jj * 8 + g]);
                mma16n8k8(o[0][jj], am[0], b0, b1);
                mma16n8k8(o[1][jj], am[1], b0, b1);
            }
        }
        __syncwarp();  // P fully consumed before next iteration overwrites
    }

    // ---- normalize + store ----
    float* Ob = O + base;
#pragma unroll
    for (int i = 0; i < 2; i++) {
        float inv0 = 1.f / lr[i][0];
        float inv1 = 1.f / lr[i][1];
        int r0 = q0 + rowb0 + i * 16;
#pragma unroll
        for (int jj = 0; jj < 8; jj++) {
            int dd = jj * 8 + 2 * t;
            *(float2*)&Ob[(size_t)r0 * D + dd] =
                make_float2(o[i][jj][0] * inv0, o[i][jj][1] * inv0);
            *(float2*)&Ob[(size_t)(r0 + 8) * D + dd] =
                make_float2(o[i][jj][2] * inv1, o[i][jj][3] * inv1);
        }
    }
}

// ---------------------------------------------------------------------------
extern "C" void kernel_launch(void* const* d_in, const int* in_sizes, int n_in,
                              void* d_out, int out_size)
{
    const float* big[3] = {nullptr, nullptr, nullptr};
    const float* w[4]   = {nullptr, nullptr, nullptr, nullptr};
    int nbig = 0, nw = 0;
    for (int i = 0; i < n_in; i++) {
        int sz = in_sizes[i];
        if (sz == M * D) {
            if (nbig < 3) big[nbig++] = (const float*)d_in[i];
        } else if (sz == D * D) {
            if (nw < 4) w[nw++] = (const float*)d_in[i];
        }
    }
    const float* q = big[0];
    const float* k = big[1];
    const float* v = big[2];
    const float* Wq = w[0];
    const float* Wk = w[1];
    const float* Wv = w[2];
    const float* Wo = w[3];
    float* out = (float*)d_out;

    float *Qp, *Kp, *Vp, *Ap;
    cudaGetSymbolAddress((void**)&Qp, g_Q);
    cudaGetSymbolAddress((void**)&Kp, g_K);
    cudaGetSymbolAddress((void**)&Vp, g_V);
    cudaGetSymbolAddress((void**)&Ap, g_A);

    cudaFuncSetAttribute(gemm_mma, cudaFuncAttributeMaxDynamicSharedMemorySize, GSM_BYTES);
    cudaFuncSetAttribute(gemm_qkv, cudaFuncAttributeMaxDynamicSharedMemorySize, GSM_BYTES);
    cudaFuncSetAttribute(flash_mma, cudaFuncAttributeMaxDynamicSharedMemorySize, FSM_BYTES);

    dim3 gq(D / 128, M / 128, 3);  // (8, 64, 3) merged QKV
    gemm_qkv<<<gq, 256, GSM_BYTES>>>(q, Wq, Qp, k, Wk, Kp, v, Wv, Vp);

    dim3 ga(S / 128, NB * H);  // (16, 64)
    flash_mma<<<ga, 128, FSM_BYTES>>>(Qp, Kp, Vp, Ap);

    dim3 gt(D / 128, M / 128);  // (8, 64)
    gemm_mma<<<gt, 256, GSM_BYTES>>>(Ap, Wo, out);
}

// round 15
// speedup vs baseline: 1.9325x; 1.7556x over previous
#include <cuda_runtime.h>
#include <cuda_fp16.h>
#include <cstdint>
#include <math.h>

// Problem constants
constexpr int NB = 4;       // batch
constexpr int S  = 2048;    // seq
constexpr int D  = 1024;    // model dim
constexpr int H  = 16;      // heads
constexpr int DK = 64;      // head dim
constexpr int M  = NB * S;  // 8192 rows

// Intermediate buffers (allocation-free rule: device globals)
__device__ float g_Q[(size_t)M * D];
__device__ float g_K[(size_t)M * D];
__device__ float g_V[(size_t)M * D];
__device__ float g_A[(size_t)M * D];

// ---------------------------------------------------------------------------
// Helpers
// ---------------------------------------------------------------------------
__device__ __forceinline__ uint32_t smem_u32(const void* p) {
    uint32_t a;
    asm("{ .reg .u64 t; cvta.to.shared.u64 t, %1; cvt.u32.u64 %0, t; }"
        : "=r"(a) : "l"(p));
    return a;
}
__device__ __forceinline__ uint32_t fp16x2(float lo, float hi) {
    __half2 h = __floats2half2_rn(lo, hi);
    return *reinterpret_cast<uint32_t*>(&h);
}
// fp16 m16n8k16 mma, fp32 accumulate
__device__ __forceinline__ void mma16(float* d, const uint32_t* a,
                                      uint32_t b0, uint32_t b1) {
    asm volatile(
        "mma.sync.aligned.m16n8k16.row.col.f32.f16.f16.f32 "
        "{%0,%1,%2,%3}, {%4,%5,%6,%7}, {%8,%9}, {%0,%1,%2,%3};"
        : "+f"(d[0]), "+f"(d[1]), "+f"(d[2]), "+f"(d[3])
        : "r"(a[0]), "r"(a[1]), "r"(a[2]), "r"(a[3]), "r"(b0), "r"(b1));
}
__device__ __forceinline__ void ldsm_x4(uint32_t* r, uint32_t addr) {
    asm volatile("ldmatrix.sync.aligned.m8n8.x4.shared.b16 {%0,%1,%2,%3}, [%4];"
                 : "=r"(r[0]), "=r"(r[1]), "=r"(r[2]), "=r"(r[3]) : "r"(addr));
}
__device__ __forceinline__ void ldsm_x2(uint32_t& r0, uint32_t& r1, uint32_t addr) {
    asm volatile("ldmatrix.sync.aligned.m8n8.x2.shared.b16 {%0,%1}, [%2];"
                 : "=r"(r0), "=r"(r1) : "r"(addr));
}
__device__ __forceinline__ void ldsm_x2t(uint32_t& r0, uint32_t& r1, uint32_t addr) {
    asm volatile("ldmatrix.sync.aligned.m8n8.x2.trans.shared.b16 {%0,%1}, [%2];"
                 : "=r"(r0), "=r"(r1) : "r"(addr));
}

// ===========================================================================
// fp16 mma GEMM: C[8192,1024] = A @ W (row-major fp32 in/out).
// 128x128 CTA tile, BK=32, 256 threads (8 warps: 4m x 2n, warp 32x64).
// smem (halves): A[128 rows][32 data, pitch 40] (5x16B odd -> conflict-free),
// B[32 rows][128 data, pitch 136] (17x16B). Double buffered, ldmatrix frags.
// ===========================================================================
constexpr int APH = 40;                   // A pitch (halves), data width 32
constexpr int BPH = 136;                  // B pitch (halves), data width 128
constexpr int ABYT = 128 * APH * 2;       // 10240
constexpr int BBYT = 32 * BPH * 2;        // 8704
constexpr int BUFB = ABYT + BBYT;         // 18944
constexpr int GSM_BYTES = 2 * BUFB;       // 37888

__device__ __forceinline__ void gemm_body(
    const float* __restrict__ A, const float* __restrict__ W,
    float* __restrict__ C, char* smc)
{
    const int tid  = threadIdx.x;
    const int lane = tid & 31;
    const int wid  = tid >> 5;
    const int wm   = wid & 3;
    const int wn   = wid >> 2;
    const int g    = lane >> 2;
    const int t    = lane & 3;
    const int m0   = blockIdx.y * 128;
    const int n0   = blockIdx.x * 128;
    const uint32_t sb = smem_u32(smc);

    float acc[2][8][4];
#pragma unroll
    for (int i = 0; i < 2; i++)
#pragma unroll
        for (int j = 0; j < 8; j++)
#pragma unroll
            for (int c = 0; c < 4; c++) acc[i][j][c] = 0.f;

    float4 ra[4], rb[4];

    auto ldg_chunk = [&](int k0) {
#pragma unroll
        for (int i = 0; i < 4; i++) {
            int id = tid + i * 256;
            int r = id >> 3, c4 = id & 7;
            ra[i] = *(const float4*)(A + (size_t)(m0 + r) * D + k0 + c4 * 4);
        }
#pragma unroll
        for (int i = 0; i < 4; i++) {
            int id = tid + i * 256;
            int r = id >> 5, c4 = id & 31;
            rb[i] = *(const float4*)(W + (size_t)(k0 + r) * D + n0 + c4 * 4);
        }
    };
    auto sts_chunk = [&](int p) {
        __half* sA = (__half*)(smc + p * BUFB);
        __half* sB = (__half*)(smc + p * BUFB + ABYT);
#pragma unroll
        for (int i = 0; i < 4; i++) {
            int id = tid + i * 256;
            int r = id >> 3, c4 = id & 7;
            uint2 u = make_uint2(fp16x2(ra[i].x, ra[i].y), fp16x2(ra[i].z, ra[i].w));
            *(uint2*)(sA + r * APH + c4 * 4) = u;
        }
#pragma unroll
        for (int i = 0; i < 4; i++) {
            int id = tid + i * 256;
            int r = id >> 5, c4 = id & 31;
            uint2 u = make_uint2(fp16x2(rb[i].x, rb[i].y), fp16x2(rb[i].z, rb[i].w));
            *(uint2*)(sB + r * BPH + c4 * 4) = u;
        }
    };

    // ldmatrix lane-address components (halves)
    const int l7  = lane & 7;
    const int ro8 = ((lane >> 3) & 1) * 8;   // x4: row offset within m16
    const int ko8 = (lane >> 4) * 8;         // x4: k offset
    const int l15_7  = lane & 7;             // x2: row within 8
    const int l15_k8 = (((lane & 15) >> 3) & 1) * 8;  // x2: second matrix k+8

    ldg_chunk(0);
    sts_chunk(0);
    __syncthreads();

    for (int ch = 0; ch < 32; ch++) {
        const int p = ch & 1;
        if (ch + 1 < 32) ldg_chunk((ch + 1) * 32);

        const uint32_t sbA = sb + p * BUFB;
        const uint32_t sbB = sbA + ABYT;
#pragma unroll
        for (int ks = 0; ks < 2; ks++) {
            const int kk = ks * 16;
            uint32_t af[2][4];
#pragma unroll
            for (int i = 0; i < 2; i++) {
                uint32_t addr = sbA + 2u * (uint32_t)(
                    (wm * 32 + i * 16 + l7 + ro8) * APH + kk + ko8);
                ldsm_x4(af[i], addr);
            }
#pragma unroll
            for (int j = 0; j < 8; j++) {
                uint32_t b0, b1;
                uint32_t addr = sbB + 2u * (uint32_t)(
                    (kk + l15_7 + l15_k8) * BPH + wn * 64 + j * 8);
                ldsm_x2t(b0, b1, addr);
                mma16(acc[0][j], af[0], b0, b1);
                mma16(acc[1][j], af[1], b0, b1);
            }
        }
        if (ch + 1 < 32) sts_chunk((ch + 1) & 1);
        __syncthreads();
    }

#pragma unroll
    for (int i = 0; i < 2; i++) {
        int row = m0 + wm * 32 + i * 16 + g;
#pragma unroll
        for (int j = 0; j < 8; j++) {
            int col = n0 + wn * 64 + j * 8 + 2 * t;
            *(float2*)&C[(size_t)row * D + col] =
                make_float2(acc[i][j][0], acc[i][j][1]);
            *(float2*)&C[(size_t)(row + 8) * D + col] =
                make_float2(acc[i][j][2], acc[i][j][3]);
        }
    }
}

__global__ __launch_bounds__(256, 2) void gemm_mma(
    const float* __restrict__ A, const float* __restrict__ W,
    float* __restrict__ C)
{
    extern __shared__ char smc[];
    gemm_body(A, W, C, smc);
}

__global__ __launch_bounds__(256, 2) void gemm_qkv(
    const float* __restrict__ A0, const float* __restrict__ W0, float* __restrict__ C0,
    const float* __restrict__ A1, const float* __restrict__ W1, float* __restrict__ C1,
    const float* __restrict__ A2, const float* __restrict__ W2, float* __restrict__ C2)
{
    extern __shared__ char smc[];
    const int z = blockIdx.z;
    const float* A = (z == 0) ? A0 : (z == 1) ? A1 : A2;
    const float* W = (z == 0) ? W0 : (z == 1) ? W1 : W2;
    float*       C = (z == 0) ? C0 : (z == 1) ? C1 : C2;
    gemm_body(A, W, C, smc);
}

// ===========================================================================
// Causal flash attention, fp16 mma + ldmatrix.
// QT=128 per CTA, 4 warps x m32n64 (B-frags amortized over 2 m-tiles).
// smem (halves): sQ[128][72], sK[64][72], sV[64][72], sP[128][72].
// PITCH 72 >= 64 data halves (the R11/R13 bug was pitch 40 < 64).
// QK: A=Q ldmatrix.x4, B=K ldmatrix.x2 (pairs along d = natural).
// PV: A=P ldmatrix.x4, B=V ldmatrix.x2.trans (pairs along token).
// sP rows warp-private -> syncwarp only between softmax and PV.
// ===========================================================================
constexpr int QPH = 72;    // Q/K/V pitch (halves), data width 64
constexpr int PPH = 72;    // P pitch (halves), data width 64
constexpr int OFF_K = 128 * QPH;            // halves
constexpr int OFF_V = OFF_K + 64 * QPH;
constexpr int OFF_P = OFF_V + 64 * QPH;
constexpr int FSM_BYTES = (OFF_P + 128 * PPH) * 2;   // 55296

__global__ __launch_bounds__(128) void flash_mma(
    const float* __restrict__ Q, const float* __restrict__ K,
    const float* __restrict__ V, float* __restrict__ O)
{
    extern __shared__ char smc[];
    __half* smh = (__half*)smc;
    __half* sQ = smh;
    __half* sK = smh + OFF_K;
    __half* sV = smh + OFF_V;
    __half* sP = smh + OFF_P;
    const uint32_t sb = smem_u32(smc);
    const uint32_t sbQ = sb;
    const uint32_t sbK = sb + OFF_K * 2;
    const uint32_t sbV = sb + OFF_V * 2;
    const uint32_t sbP = sb + OFF_P * 2;

    const int tid  = threadIdx.x;
    const int w    = tid >> 5;
    const int lane = tid & 31;
    const int g    = lane >> 2;
    const int t    = lane & 3;
    const int bh   = blockIdx.y;
    const int b    = bh >> 4;
    const int h    = bh & 15;
    const int qi   = 15 - blockIdx.x;      // heavy tiles first
    const int q0   = qi * 128;

    const size_t base = (size_t)b * S * D + (size_t)h * DK;
    const float* Qb = Q + base;
    const float* Kb = K + base;
    const float* Vb = V + base;

    // ldmatrix lane-address components
    const int l7  = lane & 7;
    const int ro8 = ((lane >> 3) & 1) * 8;
    const int ko8 = (lane >> 4) * 8;
    const int l15_7  = lane & 7;
    const int l15_k8 = (((lane & 15) >> 3) & 1) * 8;

    // Load Q tile [128][64] -> sQ (fp16): 128 rows x 16 float4
#pragma unroll
    for (int i = 0; i < 16; i++) {
        int id = tid + i * 128;
        int r = id >> 4, c = (id & 15) << 2;
        float4 v4 = *(const float4*)&Qb[(size_t)(q0 + r) * D + c];
        uint2 u = make_uint2(fp16x2(v4.x, v4.y), fp16x2(v4.z, v4.w));
        *(uint2*)(sQ + r * QPH + c) = u;
    }

    float o[2][8][4];
    float mr[2][2], lr[2][2];
#pragma unroll
    for (int i = 0; i < 2; i++) {
        mr[i][0] = -1e30f; mr[i][1] = -1e30f;
        lr[i][0] = 0.f;    lr[i][1] = 0.f;
#pragma unroll
        for (int j = 0; j < 8; j++)
#pragma unroll
            for (int c = 0; c < 4; c++) o[i][j][c] = 0.f;
    }

    const int rowb0 = w * 32 + g;
    const int nk = 2 * qi + 2;
    for (int kt = 0; kt < nk; kt++) {
        const int k0 = kt * 64;
        __syncthreads();  // prior PV done reading sK/sV
        // Load K,V tiles [64][64] -> smem (fp16): 64 rows x 16 float4 each
#pragma unroll
        for (int i = 0; i < 8; i++) {
            int id = tid + i * 128;
            int r = id >> 4, c = (id & 15) << 2;
            float4 k4 = *(const float4*)&Kb[(size_t)(k0 + r) * D + c];
            *(uint2*)(sK + r * QPH + c) = make_uint2(fp16x2(k4.x, k4.y), fp16x2(k4.z, k4.w));
            float4 v4 = *(const float4*)&Vb[(size_t)(k0 + r) * D + c];
            *(uint2*)(sV + r * QPH + c) = make_uint2(fp16x2(v4.x, v4.y), fp16x2(v4.z, v4.w));
        }
        __syncthreads();

        // ---- S = Q K^T (m32 x n64 per warp), 4 k16-steps over d=64 ----
        float s[2][8][4];
#pragma unroll
        for (int i = 0; i < 2; i++)
#pragma unroll
            for (int j = 0; j < 8; j++)
#pragma unroll
                for (int c = 0; c < 4; c++) s[i][j][c] = 0.f;

#pragma unroll
        for (int ks = 0; ks < 4; ks++) {
            const int kk = ks * 16;
            uint32_t am[2][4];
#pragma unroll
            for (int i = 0; i < 2; i++) {
                uint32_t addr = sbQ + 2u * (uint32_t)(
                    (w * 32 + i * 16 + l7 + ro8) * QPH + kk + ko8);
                ldsm_x4(am[i], addr);
            }
#pragma unroll
            for (int jj = 0; jj < 8; jj++) {
                uint32_t b0, b1;
                // K natural [token][d]; pairs along d -> non-trans.
                uint32_t addr = sbK + 2u * (uint32_t)(
                    (jj * 8 + l15_7) * QPH + kk + l15_k8);
                ldsm_x2(b0, b1, addr);
                mma16(s[0][jj], am[0], b0, b1);
                mma16(s[1][jj], am[1], b0, b1);
            }
        }

        // ---- scale + causal mask ----
        const float scale = 0.125f;  // 1/sqrt(64)
        const bool domask = (k0 >= q0);
#pragma unroll
        for (int i = 0; i < 2; i++) {
            int r0 = q0 + rowb0 + i * 16;
            int r1 = r0 + 8;
#pragma unroll
            for (int jj = 0; jj < 8; jj++) {
                int c0 = k0 + jj * 8 + 2 * t;
                int c1 = c0 + 1;
                s[i][jj][0] *= scale; s[i][jj][1] *= scale;
                s[i][jj][2] *= scale; s[i][jj][3] *= scale;
                if (domask) {
                    if (c0 > r0) s[i][jj][0] = -1e30f;
                    if (c1 > r0) s[i][jj][1] = -1e30f;
                    if (c0 > r1) s[i][jj][2] = -1e30f;
                    if (c1 > r1) s[i][jj][3] = -1e30f;
                }
            }
        }

        // ---- online softmax (rows warp-private; quad-lane reduce) ----
#pragma unroll
        for (int i = 0; i < 2; i++) {
            float mx0 = -1e30f, mx1 = -1e30f;
#pragma unroll
            for (int jj = 0; jj < 8; jj++) {
                mx0 = fmaxf(mx0, fmaxf(s[i][jj][0], s[i][jj][1]));
                mx1 = fmaxf(mx1, fmaxf(s[i][jj][2], s[i][jj][3]));
            }
            mx0 = fmaxf(mx0, __shfl_xor_sync(0xffffffffu, mx0, 1));
            mx0 = fmaxf(mx0, __shfl_xor_sync(0xffffffffu, mx0, 2));
            mx1 = fmaxf(mx1, __shfl_xor_sync(0xffffffffu, mx1, 1));
            mx1 = fmaxf(mx1, __shfl_xor_sync(0xffffffffu, mx1, 2));
            float mn0 = fmaxf(mr[i][0], mx0);
            float mn1 = fmaxf(mr[i][1], mx1);
            float al0 = __expf(mr[i][0] - mn0);
            float al1 = __expf(mr[i][1] - mn1);
            mr[i][0] = mn0; mr[i][1] = mn1;
            float rs0 = 0.f, rs1 = 0.f;
            __half* pr0 = sP + (rowb0 + i * 16) * PPH;
            __half* pr1 = pr0 + 8 * PPH;
#pragma unroll
            for (int jj = 0; jj < 8; jj++) {
                float p0 = __expf(s[i][jj][0] - mn0);
                float p1 = __expf(s[i][jj][1] - mn0);
                float p2 = __expf(s[i][jj][2] - mn1);
                float p3 = __expf(s[i][jj][3] - mn1);
                rs0 += p0 + p1;
                rs1 += p2 + p3;
                int cc = jj * 8 + 2 * t;
                *(uint32_t*)(pr0 + cc) = fp16x2(p0, p1);
                *(uint32_t*)(pr1 + cc) = fp16x2(p2, p3);
#pragma unroll
                for (int c = 0; c < 2; c++) o[i][jj][c] *= al0;
#pragma unroll
                for (int c = 2; c < 4; c++) o[i][jj][c] *= al1;
            }
            rs0 += __shfl_xor_sync(0xffffffffu, rs0, 1);
            rs0 += __shfl_xor_sync(0xffffffffu, rs0, 2);
            rs1 += __shfl_xor_sync(0xffffffffu, rs1, 1);
            rs1 += __shfl_xor_sync(0xffffffffu, rs1, 2);
            lr[i][0] = lr[i][0] * al0 + rs0;
            lr[i][1] = lr[i][1] * al1 + rs1;
        }
        __syncwarp();

        // ---- O += P V (4 k16-steps over tokens=64) ----
#pragma unroll
        for (int ks = 0; ks < 4; ks++) {
            const int kk = ks * 16;
            uint32_t am[2][4];
#pragma unroll
            for (int i = 0; i < 2; i++) {
                uint32_t addr = sbP + 2u * (uint32_t)(
                    (w * 32 + i * 16 + l7 + ro8) * PPH + kk + ko8);
                ldsm_x4(am[i], addr);
            }
#pragma unroll
            for (int jj = 0; jj < 8; jj++) {
                uint32_t b0, b1;
                // V natural [token][d]; pairs along token -> trans.
                uint32_t addr = sbV + 2u * (uint32_t)(
                    (kk + l15_7 + l15_k8) * QPH + jj * 8);
                ldsm_x2t(b0, b1, addr);
                mma16(o[0][jj], am[0], b0, b1);
                mma16(o[1][jj], am[1], b0, b1);
            }
        }
        __syncwarp();  // P fully consumed before next iteration overwrites
    }

    // ---- normalize + store ----
    float* Ob = O + base;
#pragma unroll
    for (int i = 0; i < 2; i++) {
        float inv0 = 1.f / lr[i][0];
        float inv1 = 1.f / lr[i][1];
        int r0 = q0 + rowb0 + i * 16;
#pragma unroll
        for (int jj = 0; jj < 8; jj++) {
            int dd = jj * 8 + 2 * t;
            *(float2*)&Ob[(size_t)r0 * D + dd] =
                make_float2(o[i][jj][0] * inv0, o[i][jj][1] * inv0);
            *(float2*)&Ob[(size_t)(r0 + 8) * D + dd] =
                make_float2(o[i][jj][2] * inv1, o[i][jj][3] * inv1);
        }
    }
}

// ---------------------------------------------------------------------------
extern "C" void kernel_launch(void* const* d_in, const int* in_sizes, int n_in,
                              void* d_out, int out_size)
{
    const float* big[3] = {nullptr, nullptr, nullptr};
    const float* w[4]   = {nullptr, nullptr, nullptr, nullptr};
    int nbig = 0, nw = 0;
    for (int i = 0; i < n_in; i++) {
        int sz = in_sizes[i];
        if (sz == M * D) {
            if (nbig < 3) big[nbig++] = (const float*)d_in[i];
        } else if (sz == D * D) {
            if (nw < 4) w[nw++] = (const float*)d_in[i];
        }
    }
    const float* q = big[0];
    const float* k = big[1];
    const float* v = big[2];
    const float* Wq = w[0];
    const float* Wk = w[1];
    const float* Wv = w[2];
    const float* Wo = w[3];
    float* out = (float*)d_out;

    float *Qp, *Kp, *Vp, *Ap;
    cudaGetSymbolAddress((void**)&Qp, g_Q);
    cudaGetSymbolAddress((void**)&Kp, g_K);
    cudaGetSymbolAddress((void**)&Vp, g_V);
    cudaGetSymbolAddress((void**)&Ap, g_A);

    cudaFuncSetAttribute(gemm_mma, cudaFuncAttributeMaxDynamicSharedMemorySize, GSM_BYTES);
    cudaFuncSetAttribute(gemm_qkv, cudaFuncAttributeMaxDynamicSharedMemorySize, GSM_BYTES);
    cudaFuncSetAttribute(flash_mma, cudaFuncAttributeMaxDynamicSharedMemorySize, FSM_BYTES);

    dim3 gq(D / 128, M / 128, 3);  // (8, 64, 3) merged QKV
    gemm_qkv<<<gq, 256, GSM_BYTES>>>(q, Wq, Qp, k, Wk, Kp, v, Wv, Vp);

    dim3 ga(S / 128, NB * H);  // (16, 64)
    flash_mma<<<ga, 128, FSM_BYTES>>>(Qp, Kp, Vp, Ap);

    dim3 gt(D / 128, M / 128);  // (8, 64)
    gemm_mma<<<gt, 256, GSM_BYTES>>>(Ap, Wo, out);
}

// round 17
// speedup vs baseline: 2.0253x; 1.0480x over previous
#include <cuda_runtime.h>
#include <cuda_fp16.h>
#include <cstdint>
#include <math.h>

// Problem constants
constexpr int NB = 4;       // batch
constexpr int S  = 2048;    // seq
constexpr int D  = 1024;    // model dim
constexpr int H  = 16;      // heads
constexpr int DK = 64;      // head dim
constexpr int M  = NB * S;  // 8192 rows

// Intermediate buffers — fp16 (allocation-free rule: device globals)
__device__ __half g_Q[(size_t)M * D];
__device__ __half g_K[(size_t)M * D];
__device__ __half g_V[(size_t)M * D];
__device__ __half g_A[(size_t)M * D];

// ---------------------------------------------------------------------------
// Helpers
// ---------------------------------------------------------------------------
__device__ __forceinline__ uint32_t smem_u32(const void* p) {
    uint32_t a;
    asm("{ .reg .u64 t; cvta.to.shared.u64 t, %1; cvt.u32.u64 %0, t; }"
        : "=r"(a) : "l"(p));
    return a;
}
__device__ __forceinline__ uint32_t fp16x2(float lo, float hi) {
    __half2 h = __floats2half2_rn(lo, hi);
    return *reinterpret_cast<uint32_t*>(&h);
}
__device__ __forceinline__ void mma16(float* d, const uint32_t* a,
                                      uint32_t b0, uint32_t b1) {
    asm volatile(
        "mma.sync.aligned.m16n8k16.row.col.f32.f16.f16.f32 "
        "{%0,%1,%2,%3}, {%4,%5,%6,%7}, {%8,%9}, {%0,%1,%2,%3};"
        : "+f"(d[0]), "+f"(d[1]), "+f"(d[2]), "+f"(d[3])
        : "r"(a[0]), "r"(a[1]), "r"(a[2]), "r"(a[3]), "r"(b0), "r"(b1));
}
__device__ __forceinline__ void ldsm_x4(uint32_t* r, uint32_t addr) {
    asm volatile("ldmatrix.sync.aligned.m8n8.x4.shared.b16 {%0,%1,%2,%3}, [%4];"
                 : "=r"(r[0]), "=r"(r[1]), "=r"(r[2]), "=r"(r[3]) : "r"(addr));
}
__device__ __forceinline__ void ldsm_x2(uint32_t& r0, uint32_t& r1, uint32_t addr) {
    asm volatile("ldmatrix.sync.aligned.m8n8.x2.shared.b16 {%0,%1}, [%2];"
                 : "=r"(r0), "=r"(r1) : "r"(addr));
}
__device__ __forceinline__ void ldsm_x2t(uint32_t& r0, uint32_t& r1, uint32_t addr) {
    asm volatile("ldmatrix.sync.aligned.m8n8.x2.trans.shared.b16 {%0,%1}, [%2];"
                 : "=r"(r0), "=r"(r1) : "r"(addr));
}
__device__ __forceinline__ void cp16(uint32_t dst, const void* src) {
    asm volatile("cp.async.cg.shared.global [%0], [%1], 16;"
                 :: "r"(dst), "l"(src) : "memory");
}
#define CP_COMMIT() asm volatile("cp.async.commit_group;" ::: "memory")
#define CP_WAIT0()  asm volatile("cp.async.wait_group 0;" ::: "memory")

// ===========================================================================
// QKV GEMM: C[8192,1024](fp16) = A(fp32) @ W(fp32).  (R15 passing config +
// fp16 epilogue.) 128x128 tile, BK=32, 256 thr, ldmatrix, double buffered.
// ===========================================================================
constexpr int APH = 40;
constexpr int BPH = 136;
constexpr int ABYT = 128 * APH * 2;       // 10240
constexpr int BBYT = 32 * BPH * 2;        // 8704
constexpr int BUFB = ABYT + BBYT;         // 18944
constexpr int GSM_BYTES = 2 * BUFB;       // 37888

__global__ __launch_bounds__(256, 2) void gemm_qkv(
    const float* __restrict__ A0, const float* __restrict__ W0, __half* __restrict__ C0,
    const float* __restrict__ A1, const float* __restrict__ W1, __half* __restrict__ C1,
    const float* __restrict__ A2, const float* __restrict__ W2, __half* __restrict__ C2)
{
    extern __shared__ char smc[];
    const int z = blockIdx.z;
    const float* A = (z == 0) ? A0 : (z == 1) ? A1 : A2;
    const float* W = (z == 0) ? W0 : (z == 1) ? W1 : W2;
    __half*      C = (z == 0) ? C0 : (z == 1) ? C1 : C2;

    const int tid  = threadIdx.x;
    const int lane = tid & 31;
    const int wid  = tid >> 5;
    const int wm   = wid & 3;
    const int wn   = wid >> 2;
    const int g    = lane >> 2;
    const int t    = lane & 3;
    const int m0   = blockIdx.y * 128;
    const int n0   = blockIdx.x * 128;
    const uint32_t sb = smem_u32(smc);

    float acc[2][8][4];
#pragma unroll
    for (int i = 0; i < 2; i++)
#pragma unroll
        for (int j = 0; j < 8; j++)
#pragma unroll
            for (int c = 0; c < 4; c++) acc[i][j][c] = 0.f;

    float4 ra[4], rb[4];

    auto ldg_chunk = [&](int k0) {
#pragma unroll
        for (int i = 0; i < 4; i++) {
            int id = tid + i * 256;
            int r = id >> 3, c4 = id & 7;
            ra[i] = *(const float4*)(A + (size_t)(m0 + r) * D + k0 + c4 * 4);
        }
#pragma unroll
        for (int i = 0; i < 4; i++) {
            int id = tid + i * 256;
            int r = id >> 5, c4 = id & 31;
            rb[i] = *(const float4*)(W + (size_t)(k0 + r) * D + n0 + c4 * 4);
        }
    };
    auto sts_chunk = [&](int p) {
        __half* sA = (__half*)(smc + p * BUFB);
        __half* sB = (__half*)(smc + p * BUFB + ABYT);
#pragma unroll
        for (int i = 0; i < 4; i++) {
            int id = tid + i * 256;
            int r = id >> 3, c4 = id & 7;
            uint2 u = make_uint2(fp16x2(ra[i].x, ra[i].y), fp16x2(ra[i].z, ra[i].w));
            *(uint2*)(sA + r * APH + c4 * 4) = u;
        }
#pragma unroll
        for (int i = 0; i < 4; i++) {
            int id = tid + i * 256;
            int r = id >> 5, c4 = id & 31;
            uint2 u = make_uint2(fp16x2(rb[i].x, rb[i].y), fp16x2(rb[i].z, rb[i].w));
            *(uint2*)(sB + r * BPH + c4 * 4) = u;
        }
    };

    const int l7  = lane & 7;
    const int ro8 = ((lane >> 3) & 1) * 8;
    const int ko8 = (lane >> 4) * 8;
    const int l15_7  = lane & 7;
    const int l15_k8 = (((lane & 15) >> 3) & 1) * 8;

    ldg_chunk(0);
    sts_chunk(0);
    __syncthreads();

    for (int ch = 0; ch < 32; ch++) {
        const int p = ch & 1;
        if (ch + 1 < 32) ldg_chunk((ch + 1) * 32);

        const uint32_t sbA = sb + p * BUFB;
        const uint32_t sbB = sbA + ABYT;
#pragma unroll
        for (int ks = 0; ks < 2; ks++) {
            const int kk = ks * 16;
            uint32_t af[2][4];
#pragma unroll
            for (int i = 0; i < 2; i++) {
                uint32_t addr = sbA + 2u * (uint32_t)(
                    (wm * 32 + i * 16 + l7 + ro8) * APH + kk + ko8);
                ldsm_x4(af[i], addr);
            }
#pragma unroll
            for (int j = 0; j < 8; j++) {
                uint32_t b0, b1;
                uint32_t addr = sbB + 2u * (uint32_t)(
                    (kk + l15_7 + l15_k8) * BPH + wn * 64 + j * 8);
                ldsm_x2t(b0, b1, addr);
                mma16(acc[0][j], af[0], b0, b1);
                mma16(acc[1][j], af[1], b0, b1);
            }
        }
        if (ch + 1 < 32) sts_chunk((ch + 1) & 1);
        __syncthreads();
    }

#pragma unroll
    for (int i = 0; i < 2; i++) {
        int row = m0 + wm * 32 + i * 16 + g;
#pragma unroll
        for (int j = 0; j < 8; j++) {
            int col = n0 + wn * 64 + j * 8 + 2 * t;
            *(uint32_t*)&C[(size_t)row * D + col] = fp16x2(acc[i][j][0], acc[i][j][1]);
            *(uint32_t*)&C[(size_t)(row + 8) * D + col] = fp16x2(acc[i][j][2], acc[i][j][3]);
        }
    }
}

// ===========================================================================
// O GEMM: out[8192,1024](fp32) = A(fp16) @ W(fp32).
// A tiles (128 rows x 32 halves = 64B/row = 4x16B) via cp.async; W reg-staged.
// ===========================================================================
__global__ __launch_bounds__(256, 2) void gemm_o(
    const __half* __restrict__ A, const float* __restrict__ W,
    float* __restrict__ C)
{
    extern __shared__ char smc[];
    const int tid  = threadIdx.x;
    const int lane = tid & 31;
    const int wid  = tid >> 5;
    const int wm   = wid & 3;
    const int wn   = wid >> 2;
    const int g    = lane >> 2;
    const int t    = lane & 3;
    const int m0   = blockIdx.y * 128;
    const int n0   = blockIdx.x * 128;
    const uint32_t sb = smem_u32(smc);

    float acc[2][8][4];
#pragma unroll
    for (int i = 0; i < 2; i++)
#pragma unroll
        for (int j = 0; j < 8; j++)
#pragma unroll
            for (int c = 0; c < 4; c++) acc[i][j][c] = 0.f;

    float4 rb[4];

    auto issueA = [&](int k0, int p) {
        uint32_t dstA = sb + p * BUFB;
#pragma unroll
        for (int i = 0; i < 2; i++) {
            int id = tid + i * 256;          // 0..511
            int r = id >> 2, c = id & 3;     // row 0..127, chunk 0..3 (32 halves)
            cp16(dstA + (uint32_t)(r * APH * 2 + c * 16),
                 (const char*)A + ((size_t)(m0 + r) * D + k0) * 2 + c * 16);
        }
    };
    auto ldgW = [&](int k0) {
#pragma unroll
        for (int i = 0; i < 4; i++) {
            int id = tid + i * 256;
            int r = id >> 5, c4 = id & 31;
            rb[i] = *(const float4*)(W + (size_t)(k0 + r) * D + n0 + c4 * 4);
        }
    };
    auto stsW = [&](int p) {
        __half* sB = (__half*)(smc + p * BUFB + ABYT);
#pragma unroll
        for (int i = 0; i < 4; i++) {
            int id = tid + i * 256;
            int r = id >> 5, c4 = id & 31;
            uint2 u = make_uint2(fp16x2(rb[i].x, rb[i].y), fp16x2(rb[i].z, rb[i].w));
            *(uint2*)(sB + r * BPH + c4 * 4) = u;
        }
    };

    const int l7  = lane & 7;
    const int ro8 = ((lane >> 3) & 1) * 8;
    const int ko8 = (lane >> 4) * 8;
    const int l15_7  = lane & 7;
    const int l15_k8 = (((lane & 15) >> 3) & 1) * 8;

    issueA(0, 0);
    CP_COMMIT();
    ldgW(0);
    stsW(0);
    CP_WAIT0();
    __syncthreads();

    for (int ch = 0; ch < 32; ch++) {
        const int p = ch & 1;
        if (ch + 1 < 32) {
            ldgW((ch + 1) * 32);
            issueA((ch + 1) * 32, (ch + 1) & 1);
            CP_COMMIT();
        }

        const uint32_t sbA = sb + p * BUFB;
        const uint32_t sbB = sbA + ABYT;
#pragma unroll
        for (int ks = 0; ks < 2; ks++) {
            const int kk = ks * 16;
            uint32_t af[2][4];
#pragma unroll
            for (int i = 0; i < 2; i++) {
                uint32_t addr = sbA + 2u * (uint32_t)(
                    (wm * 32 + i * 16 + l7 + ro8) * APH + kk + ko8);
                ldsm_x4(af[i], addr);
            }
#pragma unroll
            for (int j = 0; j < 8; j++) {
                uint32_t b0, b1;
                uint32_t addr = sbB + 2u * (uint32_t)(
                    (kk + l15_7 + l15_k8) * BPH + wn * 64 + j * 8);
                ldsm_x2t(b0, b1, addr);
                mma16(acc[0][j], af[0], b0, b1);
                mma16(acc[1][j], af[1], b0, b1);
            }
        }
        if (ch + 1 < 32) stsW((ch + 1) & 1);
        CP_WAIT0();
        __syncthreads();
    }

#pragma unroll
    for (int i = 0; i < 2; i++) {
        int row = m0 + wm * 32 + i * 16 + g;
#pragma unroll
        for (int j = 0; j < 8; j++) {
            int col = n0 + wn * 64 + j * 8 + 2 * t;
            *(float2*)&C[(size_t)row * D + col] =
                make_float2(acc[i][j][0], acc[i][j][1]);
            *(float2*)&C[(size_t)(row + 8) * D + col] =
                make_float2(acc[i][j][2], acc[i][j][3]);
        }
    }
}

// ===========================================================================
// Causal flash attention, fp16 in/out, mma + ldmatrix + cp.async K/V pipeline.
// QT=128 per CTA, 4 warps x m32n64. smem (halves, pitch 72):
//   sQ[128], sK[2][64], sV[2][64], sP[128]  -> 73728 B.
// NOTE: fp16 rows of d=64 are 128 BYTES = 8 x 16B chunks (R16 bug was 4).
// ===========================================================================
constexpr int QPH = 72;
constexpr int KBUF = 64 * QPH;              // one K or V buffer (halves)
constexpr int OFF_K = 128 * QPH;            // 9216
constexpr int OFF_V = OFF_K + 2 * KBUF;     // 18432
constexpr int OFF_P = OFF_V + 2 * KBUF;     // 27648
constexpr int PPH = 72;
constexpr int FSM_BYTES = (OFF_P + 128 * PPH) * 2;   // 73728

__global__ __launch_bounds__(128) void flash_mma(
    const __half* __restrict__ Q, const __half* __restrict__ K,
    const __half* __restrict__ V, __half* __restrict__ O)
{
    extern __shared__ char smc[];
    __half* smh = (__half*)smc;
    __half* sQ = smh;
    __half* sP = smh + OFF_P;
    const uint32_t sb = smem_u32(smc);
    const uint32_t sbQ = sb;
    const uint32_t sbK = sb + OFF_K * 2;
    const uint32_t sbV = sb + OFF_V * 2;
    const uint32_t sbP = sb + OFF_P * 2;

    const int tid  = threadIdx.x;
    const int w    = tid >> 5;
    const int lane = tid & 31;
    const int g    = lane >> 2;
    const int t    = lane & 3;
    const int bh   = blockIdx.y;
    const int b    = bh >> 4;
    const int h    = bh & 15;
    const int qi   = 15 - blockIdx.x;      // heavy tiles first
    const int q0   = qi * 128;

    const size_t base = (size_t)b * S * D + (size_t)h * DK;
    const __half* Qb = Q + base;
    const char* Kb = (const char*)(K + base);
    const char* Vb = (const char*)(V + base);

    const int l7  = lane & 7;
    const int ro8 = ((lane >> 3) & 1) * 8;
    const int ko8 = (lane >> 4) * 8;
    const int l15_7  = lane & 7;
    const int l15_k8 = (((lane & 15) >> 3) & 1) * 8;

    // Issue K+V tile into buffer p: 64 rows x 8 chunks of 16B per tensor.
    // 512 chunks/tensor, 128 threads -> 4 iters, K+V both per iter.
    auto issue_kv = [&](int k0, int p) {
        uint32_t dK = sbK + (uint32_t)(p * KBUF * 2);
        uint32_t dV = sbV + (uint32_t)(p * KBUF * 2);
#pragma unroll
        for (int i = 0; i < 4; i++) {
            int id = tid + i * 128;          // 0..511
            int r = id >> 3, c = id & 7;     // row 0..63, chunk 0..7 (128B/row)
            uint32_t soff = (uint32_t)(r * QPH * 2 + c * 16);
            size_t goff = (size_t)(k0 + r) * D * 2 + c * 16;
            cp16(dK + soff, Kb + goff);
            cp16(dV + soff, Vb + goff);
        }
    };

    // Load Q tile [128][64] fp16 -> sQ: 128 rows x 8 x 16B chunks
#pragma unroll
    for (int i = 0; i < 8; i++) {
        int id = tid + i * 128;              // 0..1023
        int r = id >> 3, c = (id & 7) * 16;  // row 0..127, byte chunk 0..112
        *(uint4*)((char*)sQ + r * QPH * 2 + c) =
            *(const uint4*)((const char*)Qb + (size_t)(q0 + r) * D * 2 + c);
    }

    float o[2][8][4];
    float mr[2][2], lr[2][2];
#pragma unroll
    for (int i = 0; i < 2; i++) {
        mr[i][0] = -1e30f; mr[i][1] = -1e30f;
        lr[i][0] = 0.f;    lr[i][1] = 0.f;
#pragma unroll
        for (int j = 0; j < 8; j++)
#pragma unroll
            for (int c = 0; c < 4; c++) o[i][j][c] = 0.f;
    }

    const int rowb0 = w * 32 + g;
    const int nk = 2 * qi + 2;

    issue_kv(0, 0);
    CP_COMMIT();

    for (int kt = 0; kt < nk; kt++) {
        const int p = kt & 1;
        CP_WAIT0();          // tile kt landed
        __syncthreads();     // all threads' cp.async visible; guards reuse
        if (kt + 1 < nk) {
            issue_kv((kt + 1) * 64, p ^ 1);
            CP_COMMIT();
        }

        const uint32_t cK = sbK + (uint32_t)(p * KBUF * 2);
        const uint32_t cV = sbV + (uint32_t)(p * KBUF * 2);
        const int k0 = kt * 64;

        // ---- S = Q K^T ----
        float s[2][8][4];
#pragma unroll
        for (int i = 0; i < 2; i++)
#pragma unroll
            for (int j = 0; j < 8; j++)
#pragma unroll
                for (int c = 0; c < 4; c++) s[i][j][c] = 0.f;

#pragma unroll
        for (int ks = 0; ks < 4; ks++) {
            const int kk = ks * 16;
            uint32_t am[2][4];
#pragma unroll
            for (int i = 0; i < 2; i++) {
                uint32_t addr = sbQ + 2u * (uint32_t)(
                    (w * 32 + i * 16 + l7 + ro8) * QPH + kk + ko8);
                ldsm_x4(am[i], addr);
            }
#pragma unroll
            for (int jj = 0; jj < 8; jj++) {
                uint32_t b0, b1;
                uint32_t addr = cK + 2u * (uint32_t)(
                    (jj * 8 + l15_7) * QPH + kk + l15_k8);
                ldsm_x2(b0, b1, addr);
                mma16(s[0][jj], am[0], b0, b1);
                mma16(s[1][jj], am[1], b0, b1);
            }
        }

        // ---- scale + causal mask ----
        const float scale = 0.125f;
        const bool domask = (k0 >= q0);
#pragma unroll
        for (int i = 0; i < 2; i++) {
            int r0 = q0 + rowb0 + i * 16;
            int r1 = r0 + 8;
#pragma unroll
            for (int jj = 0; jj < 8; jj++) {
                int c0 = k0 + jj * 8 + 2 * t;
                int c1 = c0 + 1;
                s[i][jj][0] *= scale; s[i][jj][1] *= scale;
                s[i][jj][2] *= scale; s[i][jj][3] *= scale;
                if (domask) {
                    if (c0 > r0) s[i][jj][0] = -1e30f;
                    if (c1 > r0) s[i][jj][1] = -1e30f;
                    if (c0 > r1) s[i][jj][2] = -1e30f;
                    if (c1 > r1) s[i][jj][3] = -1e30f;
                }
            }
        }

        // ---- online softmax (rows warp-private; quad-lane reduce) ----
#pragma unroll
        for (int i = 0; i < 2; i++) {
            float mx0 = -1e30f, mx1 = -1e30f;
#pragma unroll
            for (int jj = 0; jj < 8; jj++) {
                mx0 = fmaxf(mx0, fmaxf(s[i][jj][0], s[i][jj][1]));
                mx1 = fmaxf(mx1, fmaxf(s[i][jj][2], s[i][jj][3]));
            }
            mx0 = fmaxf(mx0, __shfl_xor_sync(0xffffffffu, mx0, 1));
            mx0 = fmaxf(mx0, __shfl_xor_sync(0xffffffffu, mx0, 2));
            mx1 = fmaxf(mx1, __shfl_xor_sync(0xffffffffu, mx1, 1));
            mx1 = fmaxf(mx1, __shfl_xor_sync(0xffffffffu, mx1, 2));
            float mn0 = fmaxf(mr[i][0], mx0);
            float mn1 = fmaxf(mr[i][1], mx1);
            float al0 = __expf(mr[i][0] - mn0);
            float al1 = __expf(mr[i][1] - mn1);
            mr[i][0] = mn0; mr[i][1] = mn1;
            float rs0 = 0.f, rs1 = 0.f;
            __half* pr0 = sP + (rowb0 + i * 16) * PPH;
            __half* pr1 = pr0 + 8 * PPH;
#pragma unroll
            for (int jj = 0; jj < 8; jj++) {
                float p0 = __expf(s[i][jj][0] - mn0);
                float p1 = __expf(s[i][jj][1] - mn0);
                float p2 = __expf(s[i][jj][2] - mn1);
                float p3 = __expf(s[i][jj][3] - mn1);
                rs0 += p0 + p1;
                rs1 += p2 + p3;
                int cc = jj * 8 + 2 * t;
                *(uint32_t*)(pr0 + cc) = fp16x2(p0, p1);
                *(uint32_t*)(pr1 + cc) = fp16x2(p2, p3);
#pragma unroll
                for (int c = 0; c < 2; c++) o[i][jj][c] *= al0;
#pragma unroll
                for (int c = 2; c < 4; c++) o[i][jj][c] *= al1;
            }
            rs0 += __shfl_xor_sync(0xffffffffu, rs0, 1);
            rs0 += __shfl_xor_sync(0xffffffffu, rs0, 2);
            rs1 += __shfl_xor_sync(0xffffffffu, rs1, 1);
            rs1 += __shfl_xor_sync(0xffffffffu, rs1, 2);
            lr[i][0] = lr[i][0] * al0 + rs0;
            lr[i][1] = lr[i][1] * al1 + rs1;
        }
        __syncwarp();

        // ---- O += P V ----
#pragma unroll
        for (int ks = 0; ks < 4; ks++) {
            const int kk = ks * 16;
            uint32_t am[2][4];
#pragma unroll
            for (int i = 0; i < 2; i++) {
                uint32_t addr = sbP + 2u * (uint32_t)(
                    (w * 32 + i * 16 + l7 + ro8) * PPH + kk + ko8);
                ldsm_x4(am[i], addr);
            }
#pragma unroll
            for (int jj = 0; jj < 8; jj++) {
                uint32_t b0, b1;
                uint32_t addr = cV + 2u * (uint32_t)(
                    (kk + l15_7 + l15_k8) * QPH + jj * 8);
                ldsm_x2t(b0, b1, addr);
                mma16(o[0][jj], am[0], b0, b1);
                mma16(o[1][jj], am[1], b0, b1);
            }
        }
        __syncwarp();  // P consumed before next softmax overwrites
    }

    // ---- normalize + store fp16 ----
    __half* Ob = O + base;
#pragma unroll
    for (int i = 0; i < 2; i++) {
        float inv0 = 1.f / lr[i][0];
        float inv1 = 1.f / lr[i][1];
        int r0 = q0 + rowb0 + i * 16;
#pragma unroll
        for (int jj = 0; jj < 8; jj++) {
            int dd = jj * 8 + 2 * t;
            *(uint32_t*)&Ob[(size_t)r0 * D + dd] =
                fp16x2(o[i][jj][0] * inv0, o[i][jj][1] * inv0);
            *(uint32_t*)&Ob[(size_t)(r0 + 8) * D + dd] =
                fp16x2(o[i][jj][2] * inv1, o[i][jj][3] * inv1);
        }
    }
}

// ---------------------------------------------------------------------------
extern "C" void kernel_launch(void* const* d_in, const int* in_sizes, int n_in,
                              void* d_out, int out_size)
{
    const float* big[3] = {nullptr, nullptr, nullptr};
    const float* w[4]   = {nullptr, nullptr, nullptr, nullptr};
    int nbig = 0, nw = 0;
    for (int i = 0; i < n_in; i++) {
        int sz = in_sizes[i];
        if (sz == M * D) {
            if (nbig < 3) big[nbig++] = (const float*)d_in[i];
        } else if (sz == D * D) {
            if (nw < 4) w[nw++] = (const float*)d_in[i];
        }
    }
    const float* q = big[0];
    const float* k = big[1];
    const float* v = big[2];
    const float* Wq = w[0];
    const float* Wk = w[1];
    const float* Wv = w[2];
    const float* Wo = w[3];
    float* out = (float*)d_out;

    __half *Qp, *Kp, *Vp, *Ap;
    cudaGetSymbolAddress((void**)&Qp, g_Q);
    cudaGetSymbolAddress((void**)&Kp, g_K);
    cudaGetSymbolAddress((void**)&Vp, g_V);
    cudaGetSymbolAddress((void**)&Ap, g_A);

    cudaFuncSetAttribute(gemm_qkv, cudaFuncAttributeMaxDynamicSharedMemorySize, GSM_BYTES);
    cudaFuncSetAttribute(gemm_o,   cudaFuncAttributeMaxDynamicSharedMemorySize, GSM_BYTES);
    cudaFuncSetAttribute(flash_mma, cudaFuncAttributeMaxDynamicSharedMemorySize, FSM_BYTES);

    dim3 gq(D / 128, M / 128, 3);  // (8, 64, 3) merged QKV
    gemm_qkv<<<gq, 256, GSM_BYTES>>>(q, Wq, Qp, k, Wk, Kp, v, Wv, Vp);

    dim3 ga(S / 128, NB * H);  // (16, 64)
    flash_mma<<<ga, 128, FSM_BYTES>>>(Qp, Kp, Vp, Ap);

    dim3 gt(D / 128, M / 128);  // (8, 64)
    gemm_o<<<gt, 256, GSM_BYTES>>>(Ap, Wo, out);
}